// round 15
// baseline (speedup 1.0000x reference)
#include <cuda_runtime.h>
#include <cuda_fp16.h>
#include <math.h>
#include <stdint.h>

// dims: tokens [2048,80] i32, emb [10000,100] f32, Wx0 [100,256], Wx1 [256,256],
// Wh [2,256,256], b [2,256], h0 [2,2048,256], Wo [256,1], bo [1] -> out [2048,1] f32

#define T_ 80
#define BS_ 2048
#define U_ 256
#define E_ 100
#define EP_ 112
#define V_ 10000

#define WPAD 264      // smem k-stride for 256-wide (conflict-free ldmatrix)
#define EPS_ 120      // smem k-stride for 112-wide

// ---------------- scratch ----------------
__device__ __half g_emb16[V_ * EP_];
__device__ __half g_Wx0T[U_ * EP_];
__device__ __half g_WT0[U_ * U_];              // Wh0^T [n][k]
__device__ __half g_WT1[U_ * U_];              // Wx1^T [n][k]
__device__ __half g_WT2[U_ * U_];              // Wh1^T [n][k]
__device__ __half g_Z1h[(size_t)T_ * BS_ * U_]; // h0@Wx1+b1 (fp16)

// ---------------- helpers ----------------
__device__ __forceinline__ void ldsm4(uint32_t &r0, uint32_t &r1, uint32_t &r2,
                                      uint32_t &r3, uint32_t addr) {
    asm volatile("ldmatrix.sync.aligned.m8n8.x4.shared.b16 {%0,%1,%2,%3}, [%4];\n"
                 : "=r"(r0), "=r"(r1), "=r"(r2), "=r"(r3) : "r"(addr));
}

__device__ __forceinline__ void mma16816(float c[4], uint32_t a0, uint32_t a1,
                                         uint32_t a2, uint32_t a3,
                                         uint32_t b0, uint32_t b1) {
    asm volatile(
        "mma.sync.aligned.m16n8k16.row.col.f32.f16.f16.f32 "
        "{%0,%1,%2,%3},{%4,%5,%6,%7},{%8,%9},{%0,%1,%2,%3};\n"
        : "+f"(c[0]), "+f"(c[1]), "+f"(c[2]), "+f"(c[3])
        : "r"(a0), "r"(a1), "r"(a2), "r"(a3), "r"(b0), "r"(b1));
}

__device__ __forceinline__ float ftanh(float x) {
    float y;
    asm("tanh.approx.f32 %0, %1;" : "=f"(y) : "f"(x));
    return y;
}

// ---------------- K0: prep (vectorized emb conversion) ----------------
__global__ void k_prep(const float* __restrict__ emb, const float* __restrict__ Wx0,
                       const float* __restrict__ Wx1, const float* __restrict__ Wh) {
    int i = blockIdx.x * 256 + threadIdx.x;
    // emb: one thread converts 8 halves (uint4 store)
    if (i < V_ * 14) {
        int v = i / 14, c8 = i - v * 14;
        __half h8[8];
        if (c8 < 12) {
            float4 f0 = *(const float4*)(emb + (size_t)v * E_ + c8 * 8);
            float4 f1 = *(const float4*)(emb + (size_t)v * E_ + c8 * 8 + 4);
            h8[0] = __float2half(f0.x); h8[1] = __float2half(f0.y);
            h8[2] = __float2half(f0.z); h8[3] = __float2half(f0.w);
            h8[4] = __float2half(f1.x); h8[5] = __float2half(f1.y);
            h8[6] = __float2half(f1.z); h8[7] = __float2half(f1.w);
        } else if (c8 == 12) {
            float4 f0 = *(const float4*)(emb + (size_t)v * E_ + 96);
            h8[0] = __float2half(f0.x); h8[1] = __float2half(f0.y);
            h8[2] = __float2half(f0.z); h8[3] = __float2half(f0.w);
            h8[4] = h8[5] = h8[6] = h8[7] = __float2half(0.0f);
        } else {
            for (int q = 0; q < 8; ++q) h8[q] = __float2half(0.0f);
        }
        *(uint4*)(g_emb16 + (size_t)v * EP_ + c8 * 8) = *(uint4*)h8;
    }
    if (i < U_ * U_) {
        int n = i >> 8, k = i & 255;
        g_WT0[i] = __float2half(Wh[k * U_ + n]);
        g_WT1[i] = __float2half(Wx1[k * U_ + n]);
        g_WT2[i] = __float2half(Wh[U_ * U_ + k * U_ + n]);
    }
    if (i < U_ * EP_) {
        int u = i / EP_, e = i - u * EP_;
        g_Wx0T[i] = __float2half(e < E_ ? Wx0[e * U_ + u] : 0.0f);
    }
}

// ---------------- K1: fused layer-0 (embedding GEMM + recurrence + Wx1 GEMM) ----------------
// Skewed per step t: acc = x_{t+1}@Wx0 + h_t@Wh0, zac = h_t@Wx1 -> Z1[t].
// Embedding rows gathered 2 steps ahead into double-buffered smem x-tile.
// B0 (Wh0T) + Bx (Wx0T) in regs; B1 (Wx1T) streamed from smem.
__global__ __launch_bounds__(256, 1) void k_r0f(const int* __restrict__ tokens,
                                                const float* __restrict__ h0in,
                                                const float* __restrict__ bias) {
    extern __shared__ __half sm[];
    __half* Wsm = sm;                       // 256 x 264 staging/resident
    __half* hb0 = sm + U_ * WPAD;           // 16 x 264 h double buffer
    __half* hb1 = hb0 + 16 * WPAD;
    __half* xt0 = hb1 + 16 * WPAD;          // 16 x 120 x-tile double buffer
    __half* xt1 = xt0 + 16 * EPS_;
    float*  bsm = (float*)(xt1 + 16 * EPS_); // 512 floats: b0 | b1
    const int tid = threadIdx.x;
    const int m0 = blockIdx.x * 16;
    const int lane = tid & 31, warp = tid >> 5;
    const int n0 = warp * 32;
    const uint32_t wbase = (uint32_t)__cvta_generic_to_shared(Wsm);
    const uint32_t hoff = ((lane & 15) * WPAD + (lane >> 4) * 8) * 2;
    const uint32_t hs0 = (uint32_t)__cvta_generic_to_shared(hb0);
    const uint32_t hs1 = (uint32_t)__cvta_generic_to_shared(hb1);
    const uint32_t xs0 = (uint32_t)__cvta_generic_to_shared(xt0);
    const uint32_t xs1 = (uint32_t)__cvta_generic_to_shared(xt1);
    const uint32_t xoff = ((lane & 15) * EPS_ + (lane >> 4) * 8) * 2;
    const int r = lane >> 2;
    const int gm = tid / 14, gc8 = tid - gm * 14;   // gather role (tid<224)

    // stage Wh0T; init h_{-1}; biases
    for (int i8 = tid; i8 < U_ * U_ / 8; i8 += 256) {
        int rr = i8 >> 5, c8 = i8 & 31;
        *(uint4*)(Wsm + rr * WPAD + c8 * 8) = *(const uint4*)(g_WT0 + rr * U_ + c8 * 8);
    }
    for (int i2 = tid; i2 < 16 * U_ / 2; i2 += 256) {
        int m = i2 >> 7, u2 = i2 & 127;
        float2 v = *(const float2*)(h0in + (size_t)(m0 + m) * U_ + u2 * 2);
        *(__half2*)(hb0 + m * WPAD + u2 * 2) = __floats2half2_rn(v.x, v.y);
    }
    for (int i = tid; i < 512; i += 256) bsm[i] = bias[i];
    __syncthreads();

    // B0 (Wh0T) fragments -> 128 regs
    uint32_t B0r[16][2][4];
#pragma unroll
    for (int ks = 0; ks < 16; ++ks)
#pragma unroll
        for (int p = 0; p < 2; ++p)
            ldsm4(B0r[ks][p][0], B0r[ks][p][1], B0r[ks][p][2], B0r[ks][p][3],
                  wbase + ((n0 + p * 16 + (lane & 15)) * WPAD + ks * 16 +
                           (lane >> 4) * 8) * 2);
    __syncthreads();

    // stage Wx0T (EPS_ layout); gather x_0 -> xt0, x_1 -> xt1
    for (int i8 = tid; i8 < U_ * EP_ / 8; i8 += 256) {
        int rr = i8 / 14, c8 = i8 - rr * 14;
        *(uint4*)(Wsm + rr * EPS_ + c8 * 8) = *(const uint4*)(g_Wx0T + rr * EP_ + c8 * 8);
    }
    if (tid < 224) {
        int tok0 = tokens[(m0 + gm) * T_ + 0];
        int tok1 = tokens[(m0 + gm) * T_ + 1];
        *(uint4*)(xt0 + gm * EPS_ + gc8 * 8) =
            *(const uint4*)(g_emb16 + (size_t)tok0 * EP_ + gc8 * 8);
        *(uint4*)(xt1 + gm * EPS_ + gc8 * 8) =
            *(const uint4*)(g_emb16 + (size_t)tok1 * EP_ + gc8 * 8);
    }
    __syncthreads();

    // Bx (Wx0T) fragments -> 56 regs
    uint32_t Bx[7][2][4];
#pragma unroll
    for (int ks = 0; ks < 7; ++ks)
#pragma unroll
        for (int p = 0; p < 2; ++p)
            ldsm4(Bx[ks][p][0], Bx[ks][p][1], Bx[ks][p][2], Bx[ks][p][3],
                  wbase + ((n0 + p * 16 + (lane & 15)) * EPS_ + ks * 16 +
                           (lane >> 4) * 8) * 2);
    __syncthreads();

    // stage Wx1T (WPAD layout, resident for GEMM2 streaming)
    for (int i8 = tid; i8 < U_ * U_ / 8; i8 += 256) {
        int rr = i8 >> 5, c8 = i8 & 31;
        *(uint4*)(Wsm + rr * WPAD + c8 * 8) = *(const uint4*)(g_WT1 + rr * U_ + c8 * 8);
    }
    __syncthreads();

    // ---- prologue: h_0 = tanh(x_0@Wx0 + h_{-1}@Wh0 + b0) -> hb1 ----
    {
        float acc[4][4] = {};
#pragma unroll
        for (int ks = 0; ks < 7; ++ks) {
            uint32_t a0, a1, a2, a3;
            ldsm4(a0, a1, a2, a3, xs0 + xoff + ks * 32);
            mma16816(acc[0], a0, a1, a2, a3, Bx[ks][0][0], Bx[ks][0][2]);
            mma16816(acc[1], a0, a1, a2, a3, Bx[ks][0][1], Bx[ks][0][3]);
            mma16816(acc[2], a0, a1, a2, a3, Bx[ks][1][0], Bx[ks][1][2]);
            mma16816(acc[3], a0, a1, a2, a3, Bx[ks][1][1], Bx[ks][1][3]);
        }
#pragma unroll
        for (int ks = 0; ks < 16; ++ks) {
            uint32_t a0, a1, a2, a3;
            ldsm4(a0, a1, a2, a3, hs0 + hoff + ks * 32);
            mma16816(acc[0], a0, a1, a2, a3, B0r[ks][0][0], B0r[ks][0][2]);
            mma16816(acc[1], a0, a1, a2, a3, B0r[ks][0][1], B0r[ks][0][3]);
            mma16816(acc[2], a0, a1, a2, a3, B0r[ks][1][0], B0r[ks][1][2]);
            mma16816(acc[3], a0, a1, a2, a3, B0r[ks][1][1], B0r[ks][1][3]);
        }
#pragma unroll
        for (int j = 0; j < 4; ++j) {
            int col = n0 + j * 8 + (lane & 3) * 2;
            float b0a = bsm[col], b0b = bsm[col + 1];
            *(__half2*)(hb1 + r * WPAD + col) =
                __floats2half2_rn(ftanh(acc[j][0] + b0a), ftanh(acc[j][1] + b0b));
            *(__half2*)(hb1 + (r + 8) * WPAD + col) =
                __floats2half2_rn(ftanh(acc[j][2] + b0a), ftanh(acc[j][3] + b0b));
        }
        __syncthreads();
    }

    // ---- main loop t = 0..78 ----
    for (int t = 0; t < T_ - 1; ++t) {
        // gather x_{t+2} (consumed next iteration)
        uint4 gx;
        const bool dog = (tid < 224) && (t + 2 < T_);
        if (dog) {
            int tok = tokens[(m0 + gm) * T_ + (t + 2)];
            gx = *(const uint4*)(g_emb16 + (size_t)tok * EP_ + gc8 * 8);
        }
        const uint32_t cur = ((t & 1) ? hs0 : hs1) + hoff;
        const uint32_t xcur = (((t + 1) & 1) ? xs1 : xs0) + xoff;
        float acc[4][4] = {}, zac[4][4] = {};
        // GEMM0: x_{t+1} @ Wx0
#pragma unroll
        for (int ks = 0; ks < 7; ++ks) {
            uint32_t a0, a1, a2, a3;
            ldsm4(a0, a1, a2, a3, xcur + ks * 32);
            mma16816(acc[0], a0, a1, a2, a3, Bx[ks][0][0], Bx[ks][0][2]);
            mma16816(acc[1], a0, a1, a2, a3, Bx[ks][0][1], Bx[ks][0][3]);
            mma16816(acc[2], a0, a1, a2, a3, Bx[ks][1][0], Bx[ks][1][2]);
            mma16816(acc[3], a0, a1, a2, a3, Bx[ks][1][1], Bx[ks][1][3]);
        }
        // dual GEMM: zac += h_t @ Wx1 (B1 smem) ; acc += h_t @ Wh0 (B0 regs)
#pragma unroll
        for (int ks = 0; ks < 16; ++ks) {
            uint32_t a0, a1, a2, a3;
            ldsm4(a0, a1, a2, a3, cur + ks * 32);
            uint32_t b0, b1_, b2, b3;
            ldsm4(b0, b1_, b2, b3,
                  wbase + ((n0 + (lane & 15)) * WPAD + ks * 16 + (lane >> 4) * 8) * 2);
            mma16816(zac[0], a0, a1, a2, a3, b0, b2);
            mma16816(zac[1], a0, a1, a2, a3, b1_, b3);
            ldsm4(b0, b1_, b2, b3,
                  wbase + ((n0 + 16 + (lane & 15)) * WPAD + ks * 16 + (lane >> 4) * 8) * 2);
            mma16816(zac[2], a0, a1, a2, a3, b0, b2);
            mma16816(zac[3], a0, a1, a2, a3, b1_, b3);
            mma16816(acc[0], a0, a1, a2, a3, B0r[ks][0][0], B0r[ks][0][2]);
            mma16816(acc[1], a0, a1, a2, a3, B0r[ks][0][1], B0r[ks][0][3]);
            mma16816(acc[2], a0, a1, a2, a3, B0r[ks][1][0], B0r[ks][1][2]);
            mma16816(acc[3], a0, a1, a2, a3, B0r[ks][1][1], B0r[ks][1][3]);
        }
        // store Z1[t] = zac + b1
#pragma unroll
        for (int j = 0; j < 4; ++j) {
            int col = n0 + j * 8 + (lane & 3) * 2;
            float b1a = bsm[U_ + col], b1b = bsm[U_ + col + 1];
            size_t base = ((size_t)t * BS_ + m0 + r) * U_ + col;
            *(__half2*)(g_Z1h + base) = __floats2half2_rn(zac[j][0] + b1a, zac[j][1] + b1b);
            *(__half2*)(g_Z1h + base + 8 * U_) =
                __floats2half2_rn(zac[j][2] + b1a, zac[j][3] + b1b);
        }
        // stash gathered x_{t+2}
        if (dog)
            *(uint4*)(((t & 1) ? xt1 : xt0) + gm * EPS_ + gc8 * 8) = gx;
        // epilogue: h_{t+1} = tanh(acc + b0)
        __half* hn = (t & 1) ? hb1 : hb0;
#pragma unroll
        for (int j = 0; j < 4; ++j) {
            int col = n0 + j * 8 + (lane & 3) * 2;
            float b0a = bsm[col], b0b = bsm[col + 1];
            *(__half2*)(hn + r * WPAD + col) =
                __floats2half2_rn(ftanh(acc[j][0] + b0a), ftanh(acc[j][1] + b0b));
            *(__half2*)(hn + (r + 8) * WPAD + col) =
                __floats2half2_rn(ftanh(acc[j][2] + b0a), ftanh(acc[j][3] + b0b));
        }
        __syncthreads();
    }

    // ---- tail: Z1[79] = h_79 @ Wx1 + b1 ; h_79 in hb0 ----
    {
        float zac[4][4] = {};
#pragma unroll
        for (int ks = 0; ks < 16; ++ks) {
            uint32_t a0, a1, a2, a3;
            ldsm4(a0, a1, a2, a3, hs0 + hoff + ks * 32);
            uint32_t b0, b1_, b2, b3;
            ldsm4(b0, b1_, b2, b3,
                  wbase + ((n0 + (lane & 15)) * WPAD + ks * 16 + (lane >> 4) * 8) * 2);
            mma16816(zac[0], a0, a1, a2, a3, b0, b2);
            mma16816(zac[1], a0, a1, a2, a3, b1_, b3);
            ldsm4(b0, b1_, b2, b3,
                  wbase + ((n0 + 16 + (lane & 15)) * WPAD + ks * 16 + (lane >> 4) * 8) * 2);
            mma16816(zac[2], a0, a1, a2, a3, b0, b2);
            mma16816(zac[3], a0, a1, a2, a3, b1_, b3);
        }
#pragma unroll
        for (int j = 0; j < 4; ++j) {
            int col = n0 + j * 8 + (lane & 3) * 2;
            float b1a = bsm[U_ + col], b1b = bsm[U_ + col + 1];
            size_t base = ((size_t)(T_ - 1) * BS_ + m0 + r) * U_ + col;
            *(__half2*)(g_Z1h + base) = __floats2half2_rn(zac[j][0] + b1a, zac[j][1] + b1b);
            *(__half2*)(g_Z1h + base + 8 * U_) =
                __floats2half2_rn(zac[j][2] + b1a, zac[j][3] + b1b);
        }
    }
}

// ---------------- K2: layer-1 recurrence + fused head (512 thr, 16 warps x n16) ----------------
// Z1[t+1] prefetched a full step ahead; 2-way split accumulator chains.
__global__ __launch_bounds__(512, 1) void k_r1(const float* __restrict__ h0in,
                                               const float* __restrict__ Wo,
                                               const float* __restrict__ bo,
                                               float* __restrict__ out) {
    extern __shared__ __half sm[];
    __half* Wsm = sm;
    __half* hb0 = sm + U_ * WPAD;
    __half* hb1 = hb0 + 16 * WPAD;
    __shared__ float zs[16];
    const int tid = threadIdx.x;
    const int m0 = blockIdx.x * 16;
    if (tid < 16) zs[tid] = 0.0f;
    for (int i8 = tid; i8 < U_ * U_ / 8; i8 += 512) {
        int rr = i8 >> 5, c8 = i8 & 31;
        *(uint4*)(Wsm + rr * WPAD + c8 * 8) = *(const uint4*)(g_WT2 + rr * U_ + c8 * 8);
    }
    for (int i2 = tid; i2 < 16 * U_ / 2; i2 += 512) {
        int m = i2 >> 7, u2 = i2 & 127;
        float2 v = *(const float2*)(h0in + (size_t)BS_ * U_ + (size_t)(m0 + m) * U_ + u2 * 2);
        *(__half2*)(hb0 + m * WPAD + u2 * 2) = __floats2half2_rn(v.x, v.y);
    }
    __syncthreads();

    const int lane = tid & 31, warp = tid >> 5;
    const int n0 = warp * 16;
    const uint32_t wbase = (uint32_t)__cvta_generic_to_shared(Wsm);
    const uint32_t hoff = ((lane & 15) * WPAD + (lane >> 4) * 8) * 2;
    const uint32_t hs0 = (uint32_t)__cvta_generic_to_shared(hb0);
    const uint32_t hs1 = (uint32_t)__cvta_generic_to_shared(hb1);
    const int r = lane >> 2;

    // Wh1T fragments -> 64 regs (n16 slice per warp)
    uint32_t Br[16][4];
#pragma unroll
    for (int ks = 0; ks < 16; ++ks)
        ldsm4(Br[ks][0], Br[ks][1], Br[ks][2], Br[ks][3],
              wbase + ((n0 + (lane & 15)) * WPAD + ks * 16 + (lane >> 4) * 8) * 2);

    // preload Z1[0]
    __half2 zc[2][2];
#pragma unroll
    for (int j = 0; j < 2; ++j) {
        int col = n0 + j * 8 + (lane & 3) * 2;
        size_t base = ((size_t)0 * BS_ + m0 + r) * U_ + col;
        zc[j][0] = *(const __half2*)(g_Z1h + base);
        zc[j][1] = *(const __half2*)(g_Z1h + base + 8 * U_);
    }

    for (int t = 0; t < T_; ++t) {
        // prefetch Z1[t+1] (clamped)
        __half2 zn[2][2];
        {
            int tn = (t + 1 < T_) ? t + 1 : t;
#pragma unroll
            for (int j = 0; j < 2; ++j) {
                int col = n0 + j * 8 + (lane & 3) * 2;
                size_t base = ((size_t)tn * BS_ + m0 + r) * U_ + col;
                zn[j][0] = *(const __half2*)(g_Z1h + base);
                zn[j][1] = *(const __half2*)(g_Z1h + base + 8 * U_);
            }
        }
        uint32_t ha = ((t & 1) ? hs1 : hs0) + hoff;
        // GEMM3 with split accumulator chains (2 x 8-deep)
        float acc[2][4] = {}, ac2[2][4] = {};
#pragma unroll
        for (int ks = 0; ks < 16; ++ks) {
            uint32_t a0, a1, a2, a3;
            ldsm4(a0, a1, a2, a3, ha + ks * 32);
            float (*A)[4] = (ks & 1) ? ac2 : acc;
            mma16816(A[0], a0, a1, a2, a3, Br[ks][0], Br[ks][2]);
            mma16816(A[1], a0, a1, a2, a3, Br[ks][1], Br[ks][3]);
        }
        __half* hn = (t & 1) ? hb0 : hb1;
#pragma unroll
        for (int j = 0; j < 2; ++j) {
            int col = n0 + j * 8 + (lane & 3) * 2;
            float2 za = __half22float2(zc[j][0]);
            float2 zb = __half22float2(zc[j][1]);
            float v0 = ftanh(acc[j][0] + ac2[j][0] + za.x);
            float v1 = ftanh(acc[j][1] + ac2[j][1] + za.y);
            float v2 = ftanh(acc[j][2] + ac2[j][2] + zb.x);
            float v3 = ftanh(acc[j][3] + ac2[j][3] + zb.y);
            *(__half2*)(hn + r * WPAD + col) = __floats2half2_rn(v0, v1);
            *(__half2*)(hn + (r + 8) * WPAD + col) = __floats2half2_rn(v2, v3);
            if (t == T_ - 1) {
                float w0 = __ldg(Wo + col), w1 = __ldg(Wo + col + 1);
                atomicAdd(&zs[r],     v0 * w0 + v1 * w1);
                atomicAdd(&zs[r + 8], v2 * w0 + v3 * w1);
            }
        }
        __syncthreads();
#pragma unroll
        for (int j = 0; j < 2; ++j) { zc[j][0] = zn[j][0]; zc[j][1] = zn[j][1]; }
    }
    if (tid < 16) {
        float z = zs[tid] + bo[0];
        out[m0 + tid] = 1.0f / (1.0f + expf(-z));
    }
}

// ---------------- launcher ----------------
extern "C" void kernel_launch(void* const* d_in, const int* in_sizes, int n_in,
                              void* d_out, int out_size) {
    const int*   tokens = (const int*)  d_in[0];
    const float* emb    = (const float*)d_in[1];
    const float* Wx0    = (const float*)d_in[2];
    const float* Wx1    = (const float*)d_in[3];
    const float* Wh     = (const float*)d_in[4];
    const float* b      = (const float*)d_in[5];
    const float* h0     = (const float*)d_in[6];
    const float* Wo     = (const float*)d_in[7];
    const float* bo     = (const float*)d_in[8];
    float* out = (float*)d_out;

    const int smem_r0 = (U_ * WPAD + 32 * WPAD + 32 * EPS_) * 2 + 512 * 4;  // 161792
    const int smem_r1 = (U_ * WPAD + 32 * WPAD) * 2;                        // 152064
    cudaFuncSetAttribute(k_r0f, cudaFuncAttributeMaxDynamicSharedMemorySize, smem_r0);
    cudaFuncSetAttribute(k_r1,  cudaFuncAttributeMaxDynamicSharedMemorySize, smem_r1);

    k_prep<<<(V_ * 14 + 255) / 256, 256>>>(emb, Wx0, Wx1, Wh);
    k_r0f<<<128, 256, smem_r0>>>(tokens, h0, b);
    k_r1<<<128, 512, smem_r1>>>(h0, Wo, bo, out);
}

// round 16
// speedup vs baseline: 1.0364x; 1.0364x over previous
#include <cuda_runtime.h>
#include <cuda_fp16.h>
#include <math.h>
#include <stdint.h>

// dims: tokens [2048,80] i32, emb [10000,100] f32, Wx0 [100,256], Wx1 [256,256],
// Wh [2,256,256], b [2,256], h0 [2,2048,256], Wo [256,1], bo [1] -> out [2048,1] f32

#define T_ 80
#define BS_ 2048
#define U_ 256
#define E_ 100
#define EP_ 112
#define V_ 10000

#define WPAD 264      // smem k-stride for 256-wide (conflict-free ldmatrix)
#define EPS_ 120      // smem k-stride for 112-wide

// ---------------- scratch ----------------
__device__ __half g_emb16[V_ * EP_];
__device__ __half g_Wx0T[U_ * EP_];
__device__ __half g_WT0[U_ * U_];              // Wh0^T [n][k]
__device__ __half g_WT1[U_ * U_];              // Wx1^T [n][k]
__device__ __half g_WT2[U_ * U_];              // Wh1^T [n][k]
__device__ __half g_Z1h[(size_t)T_ * BS_ * U_]; // h0@Wx1+b1 (fp16)

// ---------------- helpers ----------------
__device__ __forceinline__ void ldsm4(uint32_t &r0, uint32_t &r1, uint32_t &r2,
                                      uint32_t &r3, uint32_t addr) {
    asm volatile("ldmatrix.sync.aligned.m8n8.x4.shared.b16 {%0,%1,%2,%3}, [%4];\n"
                 : "=r"(r0), "=r"(r1), "=r"(r2), "=r"(r3) : "r"(addr));
}

__device__ __forceinline__ void mma16816(float c[4], uint32_t a0, uint32_t a1,
                                         uint32_t a2, uint32_t a3,
                                         uint32_t b0, uint32_t b1) {
    asm volatile(
        "mma.sync.aligned.m16n8k16.row.col.f32.f16.f16.f32 "
        "{%0,%1,%2,%3},{%4,%5,%6,%7},{%8,%9},{%0,%1,%2,%3};\n"
        : "+f"(c[0]), "+f"(c[1]), "+f"(c[2]), "+f"(c[3])
        : "r"(a0), "r"(a1), "r"(a2), "r"(a3), "r"(b0), "r"(b1));
}

__device__ __forceinline__ float ftanh(float x) {
    float y;
    asm("tanh.approx.f32 %0, %1;" : "=f"(y) : "f"(x));
    return y;
}

// ---------------- K0: prep ----------------
__global__ void k_prep(const float* __restrict__ emb, const float* __restrict__ Wx0,
                       const float* __restrict__ Wx1, const float* __restrict__ Wh) {
    int i = blockIdx.x * 256 + threadIdx.x;
    if (i < V_ * EP_) {
        int v = i / EP_, e = i - v * EP_;
        g_emb16[i] = __float2half(e < E_ ? emb[v * E_ + e] : 0.0f);
    }
    if (i < U_ * U_) {
        int n = i >> 8, k = i & 255;
        g_WT0[i] = __float2half(Wh[k * U_ + n]);
        g_WT1[i] = __float2half(Wx1[k * U_ + n]);
        g_WT2[i] = __float2half(Wh[U_ * U_ + k * U_ + n]);
    }
    if (i < U_ * EP_) {
        int u = i / EP_, e = i - u * EP_;
        g_Wx0T[i] = __float2half(e < E_ ? Wx0[e * U_ + u] : 0.0f);
    }
}

// ---------------- K1: fused layer-0 (embedding GEMM + recurrence + Wx1 GEMM) ----------------
// Skewed per step t: acc = x_{t+1}@Wx0 + h_t@Wh0 (triple-source accumulator),
// zac = h_t@Wx1 -> Z1[t]. Embedding rows gathered 2 steps ahead into a
// double-buffered smem x-tile. B0 (Wh0T) + Bx (Wx0T) in regs; B1 (Wx1T) from smem.
__global__ __launch_bounds__(256, 1) void k_r0f(const int* __restrict__ tokens,
                                                const float* __restrict__ h0in,
                                                const float* __restrict__ bias) {
    extern __shared__ __half sm[];
    __half* Wsm = sm;                       // 256 x 264 staging/resident
    __half* hb0 = sm + U_ * WPAD;           // 16 x 264 h double buffer
    __half* hb1 = hb0 + 16 * WPAD;
    __half* xt0 = hb1 + 16 * WPAD;          // 16 x 120 x-tile double buffer
    __half* xt1 = xt0 + 16 * EPS_;
    float*  bsm = (float*)(xt1 + 16 * EPS_); // 512 floats: b0 | b1
    const int tid = threadIdx.x;
    const int m0 = blockIdx.x * 16;
    const int lane = tid & 31, warp = tid >> 5;
    const int n0 = warp * 32;
    const uint32_t wbase = (uint32_t)__cvta_generic_to_shared(Wsm);
    const uint32_t hoff = ((lane & 15) * WPAD + (lane >> 4) * 8) * 2;
    const uint32_t hs0 = (uint32_t)__cvta_generic_to_shared(hb0);
    const uint32_t hs1 = (uint32_t)__cvta_generic_to_shared(hb1);
    const uint32_t xs0 = (uint32_t)__cvta_generic_to_shared(xt0);
    const uint32_t xs1 = (uint32_t)__cvta_generic_to_shared(xt1);
    const uint32_t xoff = ((lane & 15) * EPS_ + (lane >> 4) * 8) * 2;
    const int r = lane >> 2;
    const int gm = tid / 14, gc8 = tid - gm * 14;   // gather role (tid<224)

    // stage Wh0T; init h_{-1}; biases
    for (int i8 = tid; i8 < U_ * U_ / 8; i8 += 256) {
        int rr = i8 >> 5, c8 = i8 & 31;
        *(uint4*)(Wsm + rr * WPAD + c8 * 8) = *(const uint4*)(g_WT0 + rr * U_ + c8 * 8);
    }
    for (int i2 = tid; i2 < 16 * U_ / 2; i2 += 256) {
        int m = i2 >> 7, u2 = i2 & 127;
        float2 v = *(const float2*)(h0in + (size_t)(m0 + m) * U_ + u2 * 2);
        *(__half2*)(hb0 + m * WPAD + u2 * 2) = __floats2half2_rn(v.x, v.y);
    }
    for (int i = tid; i < 512; i += 256) bsm[i] = bias[i];
    __syncthreads();

    // B0 (Wh0T) fragments -> 128 regs
    uint32_t B0r[16][2][4];
#pragma unroll
    for (int ks = 0; ks < 16; ++ks)
#pragma unroll
        for (int p = 0; p < 2; ++p)
            ldsm4(B0r[ks][p][0], B0r[ks][p][1], B0r[ks][p][2], B0r[ks][p][3],
                  wbase + ((n0 + p * 16 + (lane & 15)) * WPAD + ks * 16 +
                           (lane >> 4) * 8) * 2);
    __syncthreads();

    // stage Wx0T (EPS_ layout) into Wsm region; gather x_0 -> xt0, x_1 -> xt1
    for (int i8 = tid; i8 < U_ * EP_ / 8; i8 += 256) {
        int rr = i8 / 14, c8 = i8 - rr * 14;
        *(uint4*)(Wsm + rr * EPS_ + c8 * 8) = *(const uint4*)(g_Wx0T + rr * EP_ + c8 * 8);
    }
    if (tid < 224) {
        int tok0 = tokens[(m0 + gm) * T_ + 0];
        int tok1 = tokens[(m0 + gm) * T_ + 1];
        *(uint4*)(xt0 + gm * EPS_ + gc8 * 8) =
            *(const uint4*)(g_emb16 + (size_t)tok0 * EP_ + gc8 * 8);
        *(uint4*)(xt1 + gm * EPS_ + gc8 * 8) =
            *(const uint4*)(g_emb16 + (size_t)tok1 * EP_ + gc8 * 8);
    }
    __syncthreads();

    // Bx (Wx0T) fragments -> 56 regs
    uint32_t Bx[7][2][4];
#pragma unroll
    for (int ks = 0; ks < 7; ++ks)
#pragma unroll
        for (int p = 0; p < 2; ++p)
            ldsm4(Bx[ks][p][0], Bx[ks][p][1], Bx[ks][p][2], Bx[ks][p][3],
                  wbase + ((n0 + p * 16 + (lane & 15)) * EPS_ + ks * 16 +
                           (lane >> 4) * 8) * 2);
    __syncthreads();

    // stage Wx1T (WPAD layout, resident for GEMM2 streaming)
    for (int i8 = tid; i8 < U_ * U_ / 8; i8 += 256) {
        int rr = i8 >> 5, c8 = i8 & 31;
        *(uint4*)(Wsm + rr * WPAD + c8 * 8) = *(const uint4*)(g_WT1 + rr * U_ + c8 * 8);
    }
    __syncthreads();

    // ---- prologue: h_0 = tanh(x_0@Wx0 + h_{-1}@Wh0 + b0) -> hb1 ----
    {
        float acc[4][4] = {};
#pragma unroll
        for (int ks = 0; ks < 7; ++ks) {
            uint32_t a0, a1, a2, a3;
            ldsm4(a0, a1, a2, a3, xs0 + xoff + ks * 32);
            mma16816(acc[0], a0, a1, a2, a3, Bx[ks][0][0], Bx[ks][0][2]);
            mma16816(acc[1], a0, a1, a2, a3, Bx[ks][0][1], Bx[ks][0][3]);
            mma16816(acc[2], a0, a1, a2, a3, Bx[ks][1][0], Bx[ks][1][2]);
            mma16816(acc[3], a0, a1, a2, a3, Bx[ks][1][1], Bx[ks][1][3]);
        }
#pragma unroll
        for (int ks = 0; ks < 16; ++ks) {
            uint32_t a0, a1, a2, a3;
            ldsm4(a0, a1, a2, a3, hs0 + hoff + ks * 32);
            mma16816(acc[0], a0, a1, a2, a3, B0r[ks][0][0], B0r[ks][0][2]);
            mma16816(acc[1], a0, a1, a2, a3, B0r[ks][0][1], B0r[ks][0][3]);
            mma16816(acc[2], a0, a1, a2, a3, B0r[ks][1][0], B0r[ks][1][2]);
            mma16816(acc[3], a0, a1, a2, a3, B0r[ks][1][1], B0r[ks][1][3]);
        }
#pragma unroll
        for (int j = 0; j < 4; ++j) {
            int col = n0 + j * 8 + (lane & 3) * 2;
            float b0a = bsm[col], b0b = bsm[col + 1];
            *(__half2*)(hb1 + r * WPAD + col) =
                __floats2half2_rn(ftanh(acc[j][0] + b0a), ftanh(acc[j][1] + b0b));
            *(__half2*)(hb1 + (r + 8) * WPAD + col) =
                __floats2half2_rn(ftanh(acc[j][2] + b0a), ftanh(acc[j][3] + b0b));
        }
        __syncthreads();
    }

    // ---- main loop t = 0..78 ----
    // h_t in hb1 (even t) / hb0 (odd t); x_{t+1} in xt[(t+1)&1].
    for (int t = 0; t < T_ - 1; ++t) {
        // gather x_{t+2} (consumed next iteration)
        uint4 gx;
        const bool dog = (tid < 224) && (t + 2 < T_);
        if (dog) {
            int tok = tokens[(m0 + gm) * T_ + (t + 2)];
            gx = *(const uint4*)(g_emb16 + (size_t)tok * EP_ + gc8 * 8);
        }
        const uint32_t cur = ((t & 1) ? hs0 : hs1) + hoff;
        const uint32_t xcur = (((t + 1) & 1) ? xs1 : xs0) + xoff;
        float acc[4][4] = {}, zac[4][4] = {};
        // GEMM0: x_{t+1} @ Wx0 (A from x-tile, Bx in regs)
#pragma unroll
        for (int ks = 0; ks < 7; ++ks) {
            uint32_t a0, a1, a2, a3;
            ldsm4(a0, a1, a2, a3, xcur + ks * 32);
            mma16816(acc[0], a0, a1, a2, a3, Bx[ks][0][0], Bx[ks][0][2]);
            mma16816(acc[1], a0, a1, a2, a3, Bx[ks][0][1], Bx[ks][0][3]);
            mma16816(acc[2], a0, a1, a2, a3, Bx[ks][1][0], Bx[ks][1][2]);
            mma16816(acc[3], a0, a1, a2, a3, Bx[ks][1][1], Bx[ks][1][3]);
        }
        // dual GEMM: zac += h_t @ Wx1 (B1 smem) ; acc += h_t @ Wh0 (B0 regs)
#pragma unroll
        for (int ks = 0; ks < 16; ++ks) {
            uint32_t a0, a1, a2, a3;
            ldsm4(a0, a1, a2, a3, cur + ks * 32);
            uint32_t b0, b1_, b2, b3;
            ldsm4(b0, b1_, b2, b3,
                  wbase + ((n0 + (lane & 15)) * WPAD + ks * 16 + (lane >> 4) * 8) * 2);
            mma16816(zac[0], a0, a1, a2, a3, b0, b2);
            mma16816(zac[1], a0, a1, a2, a3, b1_, b3);
            ldsm4(b0, b1_, b2, b3,
                  wbase + ((n0 + 16 + (lane & 15)) * WPAD + ks * 16 + (lane >> 4) * 8) * 2);
            mma16816(zac[2], a0, a1, a2, a3, b0, b2);
            mma16816(zac[3], a0, a1, a2, a3, b1_, b3);
            mma16816(acc[0], a0, a1, a2, a3, B0r[ks][0][0], B0r[ks][0][2]);
            mma16816(acc[1], a0, a1, a2, a3, B0r[ks][0][1], B0r[ks][0][3]);
            mma16816(acc[2], a0, a1, a2, a3, B0r[ks][1][0], B0r[ks][1][2]);
            mma16816(acc[3], a0, a1, a2, a3, B0r[ks][1][1], B0r[ks][1][3]);
        }
        // store Z1[t] = zac + b1
#pragma unroll
        for (int j = 0; j < 4; ++j) {
            int col = n0 + j * 8 + (lane & 3) * 2;
            float b1a = bsm[U_ + col], b1b = bsm[U_ + col + 1];
            size_t base = ((size_t)t * BS_ + m0 + r) * U_ + col;
            *(__half2*)(g_Z1h + base) = __floats2half2_rn(zac[j][0] + b1a, zac[j][1] + b1b);
            *(__half2*)(g_Z1h + base + 8 * U_) =
                __floats2half2_rn(zac[j][2] + b1a, zac[j][3] + b1b);
        }
        // stash gathered x_{t+2} into x-tile[t&1] (x_t's slot, already consumed)
        if (dog)
            *(uint4*)(((t & 1) ? xt1 : xt0) + gm * EPS_ + gc8 * 8) = gx;
        // epilogue: h_{t+1} = tanh(acc + b0)
        __half* hn = (t & 1) ? hb1 : hb0;
#pragma unroll
        for (int j = 0; j < 4; ++j) {
            int col = n0 + j * 8 + (lane & 3) * 2;
            float b0a = bsm[col], b0b = bsm[col + 1];
            *(__half2*)(hn + r * WPAD + col) =
                __floats2half2_rn(ftanh(acc[j][0] + b0a), ftanh(acc[j][1] + b0b));
            *(__half2*)(hn + (r + 8) * WPAD + col) =
                __floats2half2_rn(ftanh(acc[j][2] + b0a), ftanh(acc[j][3] + b0b));
        }
        __syncthreads();
    }

    // ---- tail: Z1[79] = h_79 @ Wx1 + b1 ; h_79 in hb0 ----
    {
        float zac[4][4] = {};
#pragma unroll
        for (int ks = 0; ks < 16; ++ks) {
            uint32_t a0, a1, a2, a3;
            ldsm4(a0, a1, a2, a3, hs0 + hoff + ks * 32);
            uint32_t b0, b1_, b2, b3;
            ldsm4(b0, b1_, b2, b3,
                  wbase + ((n0 + (lane & 15)) * WPAD + ks * 16 + (lane >> 4) * 8) * 2);
            mma16816(zac[0], a0, a1, a2, a3, b0, b2);
            mma16816(zac[1], a0, a1, a2, a3, b1_, b3);
            ldsm4(b0, b1_, b2, b3,
                  wbase + ((n0 + 16 + (lane & 15)) * WPAD + ks * 16 + (lane >> 4) * 8) * 2);
            mma16816(zac[2], a0, a1, a2, a3, b0, b2);
            mma16816(zac[3], a0, a1, a2, a3, b1_, b3);
        }
#pragma unroll
        for (int j = 0; j < 4; ++j) {
            int col = n0 + j * 8 + (lane & 3) * 2;
            float b1a = bsm[U_ + col], b1b = bsm[U_ + col + 1];
            size_t base = ((size_t)(T_ - 1) * BS_ + m0 + r) * U_ + col;
            *(__half2*)(g_Z1h + base) = __floats2half2_rn(zac[j][0] + b1a, zac[j][1] + b1b);
            *(__half2*)(g_Z1h + base + 8 * U_) =
                __floats2half2_rn(zac[j][2] + b1a, zac[j][3] + b1b);
        }
    }
}

// ---------------- K2: layer-1 recurrence + fused head ----------------
// 256 thr, 8 warps x n32; Z1[t+1] prefetched a full step ahead; split acc chains.
__global__ __launch_bounds__(256, 1) void k_r1(const float* __restrict__ h0in,
                                               const float* __restrict__ Wo,
                                               const float* __restrict__ bo,
                                               float* __restrict__ out) {
    extern __shared__ __half sm[];
    __half* Wsm = sm;
    __half* hb0 = sm + U_ * WPAD;
    __half* hb1 = hb0 + 16 * WPAD;
    __shared__ float zs[16];
    const int tid = threadIdx.x;
    const int m0 = blockIdx.x * 16;
    if (tid < 16) zs[tid] = 0.0f;
    for (int i8 = tid; i8 < U_ * U_ / 8; i8 += 256) {
        int rr = i8 >> 5, c8 = i8 & 31;
        *(uint4*)(Wsm + rr * WPAD + c8 * 8) = *(const uint4*)(g_WT2 + rr * U_ + c8 * 8);
    }
    for (int i2 = tid; i2 < 16 * U_ / 2; i2 += 256) {
        int m = i2 >> 7, u2 = i2 & 127;
        float2 v = *(const float2*)(h0in + (size_t)BS_ * U_ + (size_t)(m0 + m) * U_ + u2 * 2);
        *(__half2*)(hb0 + m * WPAD + u2 * 2) = __floats2half2_rn(v.x, v.y);
    }
    __syncthreads();

    const int lane = tid & 31, warp = tid >> 5;
    const int n0 = warp * 32;
    const uint32_t wbase = (uint32_t)__cvta_generic_to_shared(Wsm);
    const uint32_t hoff = ((lane & 15) * WPAD + (lane >> 4) * 8) * 2;
    const uint32_t hs0 = (uint32_t)__cvta_generic_to_shared(hb0);
    const uint32_t hs1 = (uint32_t)__cvta_generic_to_shared(hb1);
    const int r = lane >> 2;

    uint32_t Br[16][2][4];
#pragma unroll
    for (int ks = 0; ks < 16; ++ks)
#pragma unroll
        for (int p = 0; p < 2; ++p)
            ldsm4(Br[ks][p][0], Br[ks][p][1], Br[ks][p][2], Br[ks][p][3],
                  wbase + ((n0 + p * 16 + (lane & 15)) * WPAD + ks * 16 +
                           (lane >> 4) * 8) * 2);

    // preload Z1[0]
    __half2 zc[4][2];
#pragma unroll
    for (int j = 0; j < 4; ++j) {
        int col = n0 + j * 8 + (lane & 3) * 2;
        size_t base = ((size_t)0 * BS_ + m0 + r) * U_ + col;
        zc[j][0] = *(const __half2*)(g_Z1h + base);
        zc[j][1] = *(const __half2*)(g_Z1h + base + 8 * U_);
    }

    for (int t = 0; t < T_; ++t) {
        // prefetch Z1[t+1] (clamped)
        __half2 zn[4][2];
        {
            int tn = (t + 1 < T_) ? t + 1 : t;
#pragma unroll
            for (int j = 0; j < 4; ++j) {
                int col = n0 + j * 8 + (lane & 3) * 2;
                size_t base = ((size_t)tn * BS_ + m0 + r) * U_ + col;
                zn[j][0] = *(const __half2*)(g_Z1h + base);
                zn[j][1] = *(const __half2*)(g_Z1h + base + 8 * U_);
            }
        }
        uint32_t ha = ((t & 1) ? hs1 : hs0) + hoff;
        // GEMM3 with split accumulator chains (2 x 8-deep)
        float acc[4][4] = {}, ac2[4][4] = {};
#pragma unroll
        for (int ks = 0; ks < 16; ++ks) {
            uint32_t a0, a1, a2, a3;
            ldsm4(a0, a1, a2, a3, ha + ks * 32);
            float (*A)[4] = (ks & 1) ? ac2 : acc;
            mma16816(A[0], a0, a1, a2, a3, Br[ks][0][0], Br[ks][0][2]);
            mma16816(A[1], a0, a1, a2, a3, Br[ks][0][1], Br[ks][0][3]);
            mma16816(A[2], a0, a1, a2, a3, Br[ks][1][0], Br[ks][1][2]);
            mma16816(A[3], a0, a1, a2, a3, Br[ks][1][1], Br[ks][1][3]);
        }
        __half* hn = (t & 1) ? hb0 : hb1;
#pragma unroll
        for (int j = 0; j < 4; ++j) {
            int col = n0 + j * 8 + (lane & 3) * 2;
            float2 za = __half22float2(zc[j][0]);
            float2 zb = __half22float2(zc[j][1]);
            float v0 = ftanh(acc[j][0] + ac2[j][0] + za.x);
            float v1 = ftanh(acc[j][1] + ac2[j][1] + za.y);
            float v2 = ftanh(acc[j][2] + ac2[j][2] + zb.x);
            float v3 = ftanh(acc[j][3] + ac2[j][3] + zb.y);
            *(__half2*)(hn + r * WPAD + col) = __floats2half2_rn(v0, v1);
            *(__half2*)(hn + (r + 8) * WPAD + col) = __floats2half2_rn(v2, v3);
            if (t == T_ - 1) {
                float w0 = __ldg(Wo + col), w1 = __ldg(Wo + col + 1);
                atomicAdd(&zs[r],     v0 * w0 + v1 * w1);
                atomicAdd(&zs[r + 8], v2 * w0 + v3 * w1);
            }
        }
        __syncthreads();
#pragma unroll
        for (int j = 0; j < 4; ++j) { zc[j][0] = zn[j][0]; zc[j][1] = zn[j][1]; }
    }
    if (tid < 16) {
        float z = zs[tid] + bo[0];
        out[m0 + tid] = 1.0f / (1.0f + expf(-z));
    }
}

// ---------------- launcher ----------------
extern "C" void kernel_launch(void* const* d_in, const int* in_sizes, int n_in,
                              void* d_out, int out_size) {
    const int*   tokens = (const int*)  d_in[0];
    const float* emb    = (const float*)d_in[1];
    const float* Wx0    = (const float*)d_in[2];
    const float* Wx1    = (const float*)d_in[3];
    const float* Wh     = (const float*)d_in[4];
    const float* b      = (const float*)d_in[5];
    const float* h0     = (const float*)d_in[6];
    const float* Wo     = (const float*)d_in[7];
    const float* bo     = (const float*)d_in[8];
    float* out = (float*)d_out;

    const int smem_r0 = (U_ * WPAD + 32 * WPAD + 32 * EPS_) * 2 + 512 * 4;  // 161792
    const int smem_r1 = (U_ * WPAD + 32 * WPAD) * 2;                        // 152064
    cudaFuncSetAttribute(k_r0f, cudaFuncAttributeMaxDynamicSharedMemorySize, smem_r0);
    cudaFuncSetAttribute(k_r1,  cudaFuncAttributeMaxDynamicSharedMemorySize, smem_r1);

    k_prep<<<(V_ * EP_ + 255) / 256, 256>>>(emb, Wx0, Wx1, Wh);
    k_r0f<<<128, 256, smem_r0>>>(tokens, h0, b);
    k_r1<<<128, 256, smem_r1>>>(h0, Wo, bo, out);
}